// round 4
// baseline (speedup 1.0000x reference)
#include <cuda_runtime.h>
#include <cstdint>
#include <cstdio>

// Problem constants
#define Bn      16384
#define Nn      17
#define Cc      128      // CIN
#define Dd      128      // COUT
#define Kk      3
#define TB      8        // batches per CTA
#define THREADS 512
#define ROWE    (Nn*Cc)  // 2176 floats per batch

// L (k=1) and T2 (k=2) live here; k=0 is identity (handled implicitly).
__device__ float g_L[2*Nn*Nn];

// ---------------------------------------------------------------------------
// Setup kernel: Chebyshev basis from adjacency (tiny, one block)
//   L = I - D^{-1/2} A D^{-1/2};  T2 = 2 L@L - I
// ---------------------------------------------------------------------------
__global__ void cheb_kernel(const float* __restrict__ adj) {
    __shared__ float dinv[Nn];
    __shared__ float Ls[Nn*Nn];
    int t = threadIdx.x;                 // 0..288
    if (t < Nn) {
        float s = 0.f;
        #pragma unroll
        for (int m = 0; m < Nn; ++m) s += adj[t*Nn + m];
        dinv[t] = 1.0f / sqrtf(s);
    }
    __syncthreads();
    if (t < Nn*Nn) {
        int n = t / Nn, m = t % Nn;
        float l = (n == m ? 1.f : 0.f) - dinv[n] * adj[t] * dinv[m];
        Ls[t] = l;
    }
    __syncthreads();
    if (t < Nn*Nn) {
        int n = t / Nn, m = t % Nn;
        float a = 0.f;
        #pragma unroll
        for (int j = 0; j < Nn; ++j) a = fmaf(Ls[n*Nn + j], Ls[j*Nn + m], a);
        g_L[t]         = Ls[t];                          // k=1: L
        g_L[Nn*Nn + t] = 2.f * a - (n == m ? 1.f : 0.f); // k=2: T2
    }
}

// ---------------------------------------------------------------------------
// Main kernel: fused aggregation + per-order transform + bias + relu
//   out[b,n,d] = relu( sum_k sum_c u_k[b,n,c] * W_k[c,d] + bias[d] )
//   u_0 = x;  u_k = T_k @ x (over node dim, N=17)
//
// smem layout (dynamic):
//   sU2 : TB*2176 float2   (each U value duplicated {u,u} for fma.rn.f32x2)
//   sW  : 128*128 float    (current W_k)
//   sL  : 2*289   float    (L, T2)
// ---------------------------------------------------------------------------
#define SMEM_U_BYTES  (TB*ROWE*8)                 // 139264
#define SMEM_W_BYTES  (Cc*Dd*4)                   // 65536
#define SMEM_L_BYTES  (2*Nn*Nn*4)                 // 2312
#define SMEM_TOTAL    (SMEM_U_BYTES + SMEM_W_BYTES + SMEM_L_BYTES)

__global__ void __launch_bounds__(THREADS, 1)
graphcheb_main(const float* __restrict__ x, const float* __restrict__ w,
               const float* __restrict__ bias, float* __restrict__ out) {
    extern __shared__ char smem[];
    float2* sU2 = (float2*)smem;                               // TB*2176 entries
    float*  sW  = (float*)(smem + SMEM_U_BYTES);               // 16384 floats
    float*  sL  = (float*)(smem + SMEM_U_BYTES + SMEM_W_BYTES);

    const int tid = threadIdx.x;
    const int b0  = blockIdx.x * TB;
    const int b   = tid >> 6;          // 0..7  (local batch)
    const int dp  = tid & 63;          // d-pair index: covers d = 2*dp, 2*dp+1
    const float2* uB = sU2 + b * ROWE;
    const float* xt  = x + (size_t)b0 * ROWE;   // contiguous 8-batch tile

    // --- prologue: L matrices, k=0 U (= dup(x)), W_0 ---
    for (int i = tid; i < 2*Nn*Nn; i += THREADS) sL[i] = g_L[i];
    for (int i = tid; i < TB*ROWE; i += THREADS) {
        float v = xt[i];
        sU2[i] = make_float2(v, v);
    }
    {
        const float4* wg = (const float4*)w;
        float4* sw4 = (float4*)sW;
        for (int i = tid; i < (Cc*Dd)/4; i += THREADS) sw4[i] = wg[i];
    }
    __syncthreads();

    // packed f32x2 accumulators: acc[n] = {out[b,n,2dp], out[b,n,2dp+1]}
    uint64_t acc[Nn];
    #pragma unroll
    for (int n = 0; n < Nn; ++n) acc[n] = 0ull;

    #pragma unroll 1
    for (int k = 0; k < Kk; ++k) {
        // ---- GEMM: acc[n] += u[b,n,c] * W_k[c, 2dp..2dp+1] over c ----
        #pragma unroll 2
        for (int c = 0; c < Cc; ++c) {
            uint64_t wv = *(const uint64_t*)(sW + c*Dd + 2*dp);   // LDS.64, lane-consecutive
            const float2* up = uB + c;
            #pragma unroll
            for (int n = 0; n < Nn; ++n) {
                uint64_t uv = *(const uint64_t*)(up + (size_t)n*Cc); // LDS.64 broadcast {u,u}
                asm("fma.rn.f32x2 %0, %1, %2, %0;" : "+l"(acc[n]) : "l"(uv), "l"(wv));
            }
        }
        if (k == Kk - 1) break;
        __syncthreads();   // everyone done with sU2/sW for this k

        // ---- stage k+1: load W_{k+1}; aggregate U_{k+1} from global x ----
        {
            const float4* wg = (const float4*)(w + (size_t)(k+1)*Cc*Dd);
            float4* sw4 = (float4*)sW;
            for (int i = tid; i < (Cc*Dd)/4; i += THREADS) sw4[i] = wg[i];
        }
        const float* Lr = sL + k*Nn*Nn;   // (k+1)-th basis stored at slot k
        #pragma unroll 1
        for (int s = 0; s < (TB*Cc)/THREADS; ++s) {   // 2 points (b,c) per thread
            int p  = tid + s*THREADS;                 // 0..1023
            int bb = p >> 7, c = p & 127;
            const float* xg = xt + bb*ROWE + c;
            float xr[Nn];
            #pragma unroll
            for (int m = 0; m < Nn; ++m) xr[m] = xg[m*Cc];   // coalesced LDG
            float2* uo = sU2 + bb*ROWE + c;
            #pragma unroll
            for (int n = 0; n < Nn; ++n) {
                float u = 0.f;
                #pragma unroll
                for (int m = 0; m < Nn; ++m) u = fmaf(Lr[n*Nn + m], xr[m], u);
                uo[(size_t)n*Cc] = make_float2(u, u);
            }
        }
        __syncthreads();
    }

    // ---- epilogue: bias + relu, coalesced float2 stores ----
    float2 bv = *(const float2*)(bias + 2*dp);
    float* og = out + (size_t)(b0 + b) * ROWE + 2*dp;
    #pragma unroll
    for (int n = 0; n < Nn; ++n) {
        float2 a = *reinterpret_cast<float2*>(&acc[n]);
        a.x = fmaxf(a.x + bv.x, 0.f);
        a.y = fmaxf(a.y + bv.y, 0.f);
        *(float2*)(og + (size_t)n*Cc) = a;
    }
}

// ---------------------------------------------------------------------------
extern "C" void kernel_launch(void* const* d_in, const int* in_sizes, int n_in,
                              void* d_out, int out_size) {
    const float* x    = (const float*)d_in[0];   // [16384,17,128]
    const float* adj  = (const float*)d_in[1];   // [17,17]
    const float* w    = (const float*)d_in[2];   // [3,1,128,128]
    const float* bias = (const float*)d_in[3];   // [1,1,128]
    float* out = (float*)d_out;                  // [16384,17,128]

    // idempotent, executes immediately (not a stream op) -> capture-safe
    cudaFuncSetAttribute(graphcheb_main,
                         cudaFuncAttributeMaxDynamicSharedMemorySize, SMEM_TOTAL);

    cheb_kernel<<<1, Nn*Nn>>>(adj);
    graphcheb_main<<<Bn/TB, THREADS, SMEM_TOTAL>>>(x, w, bias, out);
}

// round 6
// speedup vs baseline: 2.9425x; 2.9425x over previous
#include <cuda_runtime.h>
#include <cstdint>

// ---------------- problem constants ----------------
#define Bn 16384
#define Nn 17
#define Cc 128
#define Dd 128
#define THREADS 288          // 9 warps: 8 GEMM warps + full 9-batch coverage
#define ROWE 2176            // 17*128 floats per batch
#define USTRIDE 132          // A tile pad: stride % 32 == 4 -> conflict-free A frags
#define WSTRIDE 136          // B tile pad: stride % 32 == 8 -> conflict-free B frags

// ---------------- device scratch ----------------
__device__ float  g_Wt[3*Cc*WSTRIDE];   // tf32-rounded W, padded [k][c][d]
__device__ float2 g_Ldup[2*Nn*Nn];      // {l,l} duplicated for fma.rn.f32x2

// ---------------- smem float-index offsets ----------------
#define SF_U    0                       // 128*132 = 16896 floats
#define SF_W    16896                   // 128*136 = 17408
#define SF_X    34304                   // 9*2176  = 19584 (tf32-rounded x tile)
#define SF_LD   53888                   // 578 float2 = 1156 floats (8B aligned)
#define SF_BIAS 55044                   // 128
#define SMEM_FLOATS 55172
#define SMEM_BYTES  (SMEM_FLOATS*4)     // 220688

// ---------------- helpers ----------------
__device__ __forceinline__ uint32_t cvt_tf32(float f) {
    uint32_t u; asm("cvt.rn.tf32.f32 %0, %1;" : "=r"(u) : "f"(f)); return u;
}
__device__ __forceinline__ float tf32f(float f) {
    return __uint_as_float(cvt_tf32(f));
}
__device__ __forceinline__ void fma2(uint64_t& acc, uint64_t a, uint64_t b) {
    asm("fma.rn.f32x2 %0, %1, %2, %0;" : "+l"(acc) : "l"(a), "l"(b));
}
__device__ __forceinline__ void unpack2(uint64_t u, float& a, float& b) {
    asm("mov.b64 {%0, %1}, %2;" : "=f"(a), "=f"(b) : "l"(u));
}
__device__ __forceinline__ void mma_tf32(float* d, const uint32_t* a, const uint32_t* b) {
    asm volatile("mma.sync.aligned.m16n8k8.row.col.f32.tf32.tf32.f32 "
        "{%0,%1,%2,%3}, {%4,%5,%6,%7}, {%8,%9}, {%0,%1,%2,%3};"
        : "+f"(d[0]), "+f"(d[1]), "+f"(d[2]), "+f"(d[3])
        : "r"(a[0]), "r"(a[1]), "r"(a[2]), "r"(a[3]), "r"(b[0]), "r"(b[1]));
}

// ---------------------------------------------------------------------------
// Setup 1: Chebyshev basis -> duplicated-pair table g_Ldup
// ---------------------------------------------------------------------------
__global__ void cheb_kernel(const float* __restrict__ adj) {
    __shared__ float dinv[Nn];
    __shared__ float Ls[Nn*Nn];
    int t = threadIdx.x;
    if (t < Nn) {
        float s = 0.f;
        #pragma unroll
        for (int m = 0; m < Nn; ++m) s += adj[t*Nn + m];
        dinv[t] = rsqrtf(s);
    }
    __syncthreads();
    if (t < Nn*Nn) {
        int n = t / Nn, m = t % Nn;
        Ls[t] = (n == m ? 1.f : 0.f) - dinv[n] * adj[t] * dinv[m];
    }
    __syncthreads();
    if (t < Nn*Nn) {
        int n = t / Nn, m = t % Nn;
        float a = 0.f;
        #pragma unroll
        for (int j = 0; j < Nn; ++j) a = fmaf(Ls[n*Nn + j], Ls[j*Nn + m], a);
        float t2 = 2.f * a - (n == m ? 1.f : 0.f);
        g_Ldup[t]         = make_float2(Ls[t], Ls[t]);
        g_Ldup[Nn*Nn + t] = make_float2(t2, t2);
    }
}

// ---------------------------------------------------------------------------
// Setup 2: W [k][c][d] -> tf32-rounded, padded stride-136 copy in g_Wt
// ---------------------------------------------------------------------------
__global__ void wprep_kernel(const float* __restrict__ w) {
    int idx = blockIdx.x * 256 + threadIdx.x;    // over 3*128*128
    if (idx >= 3*Cc*Dd) return;
    int k = idx / (Cc*Dd), rem = idx % (Cc*Dd);
    int c = rem >> 7, d = rem & 127;
    g_Wt[(k*Cc + c)*WSTRIDE + d] = tf32f(w[idx]);
}

// ---------------------------------------------------------------------------
// Main kernel
// ---------------------------------------------------------------------------
__global__ void __launch_bounds__(THREADS, 1)
graphcheb_mma(const float* __restrict__ x, const float* __restrict__ bias,
              float* __restrict__ out) {
    extern __shared__ float sm[];
    float* sU = sm + SF_U;
    float* sW = sm + SF_W;
    float* sX = sm + SF_X;
    const uint64_t* sLd = (const uint64_t*)(sm + SF_LD);
    float* sBias = sm + SF_BIAS;

    const int t    = threadIdx.x;
    const int lane = t & 31;
    const int warp = t >> 5;                    // 0..8
    const int g    = lane >> 2;                 // fragment group row 0..7
    const int tq   = lane & 3;                  // fragment col 0..3

    const int rg0    = blockIdx.x * 128;        // first global row of tile
    const int bstart = rg0 / Nn;
    const int phase  = rg0 - bstart * Nn;       // 0..16
    const int nb     = (rg0 + 127) / Nn - bstart + 1;   // batches spanned (8 or 9)

    // ---- prologue: x tile (tf32-rounded), W0, Ldup, bias ----
    {
        const float4* xg = (const float4*)(x + (size_t)bstart * ROWE);
        float4* xs = (float4*)sX;
        for (int i = t; i < nb*544; i += THREADS) {
            float4 v = xg[i];
            v.x = tf32f(v.x); v.y = tf32f(v.y); v.z = tf32f(v.z); v.w = tf32f(v.w);
            xs[i] = v;
        }
        const float4* wg = (const float4*)g_Wt;
        float4* ws = (float4*)sW;
        for (int i = t; i < Cc*(WSTRIDE/4); i += THREADS) ws[i] = wg[i];
        float2* ls = (float2*)(sm + SF_LD);
        for (int i = t; i < 2*Nn*Nn; i += THREADS) ls[i] = g_Ldup[i];
        if (t < Dd) sBias[t] = bias[t];
    }
    __syncthreads();

    // ---- U0 = x in canonical [row][USTRIDE] layout ----
    if (warp < nb) {
        #pragma unroll
        for (int n = 0; n < Nn; ++n) {
            int r = warp*Nn + n - phase;
            if (r >= 0 && r < 128) {
                float4 v = *(const float4*)(sX + warp*ROWE + n*Cc + 4*lane);
                *(float4*)(sU + r*USTRIDE + 4*lane) = v;
            }
        }
    }
    __syncthreads();

    // ---- GEMM state (persists across the 3 chunks) ----
    const int mw = warp >> 1;                  // 0..3
    const int nw = warp & 1;                   // 0..1
    const int r0 = 32 * mw;
    const int d0 = 64 * nw;
    float acc[2][8][4];
    #pragma unroll
    for (int mi = 0; mi < 2; ++mi)
        #pragma unroll
        for (int ni = 0; ni < 8; ++ni)
            #pragma unroll
            for (int j = 0; j < 4; ++j) acc[mi][ni][j] = 0.f;

    #pragma unroll 1
    for (int k = 0; k < 3; ++k) {
        // ---- GEMM chunk k: acc += U(128x128) x W(128x128) ----
        if (warp < 8) {
            const float* uA = sU + (r0 + g)*USTRIDE + tq;
            const float* wB = sW + tq*WSTRIDE + d0 + g;
            #pragma unroll 2
            for (int s = 0; s < 16; ++s) {
                const int c0 = 8*s;
                uint32_t A[2][4];
                #pragma unroll
                for (int mi = 0; mi < 2; ++mi) {
                    const float* a = uA + mi*16*USTRIDE + c0;
                    A[mi][0] = __float_as_uint(a[0]);
                    A[mi][1] = __float_as_uint(a[8*USTRIDE]);
                    A[mi][2] = __float_as_uint(a[4]);
                    A[mi][3] = __float_as_uint(a[8*USTRIDE + 4]);
                }
                uint32_t Bf[8][2];
                const float* b = wB + c0*WSTRIDE;
                #pragma unroll
                for (int ni = 0; ni < 8; ++ni) {
                    Bf[ni][0] = __float_as_uint(b[8*ni]);
                    Bf[ni][1] = __float_as_uint(b[4*WSTRIDE + 8*ni]);
                }
                #pragma unroll
                for (int mi = 0; mi < 2; ++mi)
                    #pragma unroll
                    for (int ni = 0; ni < 8; ++ni)
                        mma_tf32(acc[mi][ni], A[mi], Bf[ni]);
            }
        }
        if (k == 2) break;
        __syncthreads();   // chunk done reading sU/sW

        // ---- aggregate U_{k+1} = T_{k+1} @ x  (warp -> batch, lane -> c quad) ----
        if (warp < nb) {
            uint64_t ag[Nn][2];
            #pragma unroll
            for (int n = 0; n < Nn; ++n) { ag[n][0] = 0ull; ag[n][1] = 0ull; }
            const uint64_t* Lk = sLd + k*Nn*Nn;
            const float* xb = sX + warp*ROWE + 4*lane;
            #pragma unroll 1
            for (int m = 0; m < Nn; ++m) {
                ulonglong2 xq = *(const ulonglong2*)(xb + m*Cc);
                #pragma unroll
                for (int n = 0; n < Nn; ++n) {
                    uint64_t l = Lk[n*Nn + m];       // LDS.64 broadcast
                    fma2(ag[n][0], xq.x, l);
                    fma2(ag[n][1], xq.y, l);
                }
            }
            #pragma unroll
            for (int n = 0; n < Nn; ++n) {
                int r = warp*Nn + n - phase;
                if (r >= 0 && r < 128) {
                    float f0, f1, f2, f3;
                    unpack2(ag[n][0], f0, f1);
                    unpack2(ag[n][1], f2, f3);
                    uint4 o;
                    o.x = cvt_tf32(f0); o.y = cvt_tf32(f1);
                    o.z = cvt_tf32(f2); o.w = cvt_tf32(f3);
                    *(uint4*)(sU + r*USTRIDE + 4*lane) = o;
                }
            }
        }
        // ---- stage W_{k+1} ----
        {
            const float4* wg = (const float4*)(g_Wt + (size_t)(k+1)*Cc*WSTRIDE);
            float4* ws = (float4*)sW;
            for (int i = t; i < Cc*(WSTRIDE/4); i += THREADS) ws[i] = wg[i];
        }
        __syncthreads();
    }

    // ---- epilogue: bias + relu, register fragments -> gmem ----
    if (warp < 8) {
        #pragma unroll
        for (int ni = 0; ni < 8; ++ni) {
            const int col = d0 + 8*ni + 2*tq;
            const float2 bv = *(const float2*)(sBias + col);
            #pragma unroll
            for (int mi = 0; mi < 2; ++mi) {
                const int rr = rg0 + r0 + 16*mi + g;
                float2 v0, v1;
                v0.x = fmaxf(acc[mi][ni][0] + bv.x, 0.f);
                v0.y = fmaxf(acc[mi][ni][1] + bv.y, 0.f);
                v1.x = fmaxf(acc[mi][ni][2] + bv.x, 0.f);
                v1.y = fmaxf(acc[mi][ni][3] + bv.y, 0.f);
                *(float2*)(out + (size_t)rr*Dd + col)       = v0;
                *(float2*)(out + (size_t)(rr + 8)*Dd + col) = v1;
            }
        }
    }
}

// ---------------------------------------------------------------------------
extern "C" void kernel_launch(void* const* d_in, const int* in_sizes, int n_in,
                              void* d_out, int out_size) {
    const float* x    = (const float*)d_in[0];   // [16384,17,128]
    const float* adj  = (const float*)d_in[1];   // [17,17]
    const float* w    = (const float*)d_in[2];   // [3,1,128,128]
    const float* bias = (const float*)d_in[3];   // [1,1,128]
    float* out = (float*)d_out;                  // [16384,17,128]

    cudaFuncSetAttribute(graphcheb_mma,
                         cudaFuncAttributeMaxDynamicSharedMemorySize, SMEM_BYTES);

    cheb_kernel<<<1, 512>>>(adj);
    wprep_kernel<<<(3*Cc*Dd + 255)/256, 256>>>(w);
    graphcheb_mma<<<(Bn*Nn)/128, THREADS, SMEM_BYTES>>>(x, bias, out);
}

// round 8
// speedup vs baseline: 3.9003x; 1.3255x over previous
#include <cuda_runtime.h>
#include <cstdint>

// ---------------- problem constants ----------------
#define Bn 16384
#define Nn 17
#define Cc 128
#define Dd 128
#define THREADS 288
#define XSTR 136               // x/U0 tile row stride (mod 32 == 8: conflict-free frags)
#define USTR 264               // U12 tile row stride (mod 32 == 8)

// ---------------- device scratch ----------------
__device__ float4 g_L12[Nn*Nn];      // {l1,l1,t2,t2} per (n,m)
__device__ float  g_WB[3*16*16*64];  // W as tf32 fragments, fully coalesced per LDG.64

// ---------------- smem float-index offsets ----------------
#define SF_XU   0                    // 153*136 = 20808 floats (x rows, pc-paired, tf32)
#define SF_U    20808                // 128*264 = 33792 floats (U1 cols 0..127 | U2 cols 128..255)
#define SF_L    54600                // 289 float4 = 1156 floats
#define SF_BIAS 55756                // 128 floats
#define SMEM_FLOATS 55884
#define SMEM_BYTES  (SMEM_FLOATS*4)  // 223536

// ---------------- helpers ----------------
__device__ __forceinline__ uint32_t cvt_tf32(float f) {
    uint32_t u; asm("cvt.rn.tf32.f32 %0, %1;" : "=r"(u) : "f"(f)); return u;
}
__device__ __forceinline__ float tf32f(float f) { return __uint_as_float(cvt_tf32(f)); }
__device__ __forceinline__ void fma2(uint64_t& acc, uint64_t a, uint64_t b) {
    asm("fma.rn.f32x2 %0, %1, %2, %0;" : "+l"(acc) : "l"(a), "l"(b));
}
__device__ __forceinline__ void unpack2(uint64_t u, float& a, float& b) {
    asm("mov.b64 {%0, %1}, %2;" : "=f"(a), "=f"(b) : "l"(u));
}
__device__ __forceinline__ uint64_t pack2f(float a, float b) {
    uint64_t u; asm("mov.b64 %0, {%1, %2};" : "=l"(u) : "f"(a), "f"(b)); return u;
}
__device__ __forceinline__ uint64_t pack2i(uint32_t a, uint32_t b) {
    uint64_t u; asm("mov.b64 %0, {%1, %2};" : "=l"(u) : "r"(a), "r"(b)); return u;
}
__device__ __forceinline__ void mma_tf32(float* d, uint32_t a0, uint32_t a1,
                                         uint32_t a2, uint32_t a3,
                                         uint32_t b0, uint32_t b1) {
    asm volatile("mma.sync.aligned.m16n8k8.row.col.f32.tf32.tf32.f32 "
        "{%0,%1,%2,%3}, {%4,%5,%6,%7}, {%8,%9}, {%0,%1,%2,%3};"
        : "+f"(d[0]), "+f"(d[1]), "+f"(d[2]), "+f"(d[3])
        : "r"(a0), "r"(a1), "r"(a2), "r"(a3), "r"(b0), "r"(b1));
}

// ---------------------------------------------------------------------------
// Merged setup: blocks 0..95 emit W fragments; block 96 computes Chebyshev basis
//   Fragment layout: g_WB[(((k*16+s)*16)+ni)*64 + lane*2 + j]
//     = tf32( W_k[c = 8s + (lane&3) + 4j][d = (lane>>2) + 8*ni] )
// ---------------------------------------------------------------------------
__global__ void setup_kernel(const float* __restrict__ adj, const float* __restrict__ w) {
    __shared__ float dinv[Nn];
    __shared__ float Ls[Nn*Nn];
    if (blockIdx.x < 96) {
        int idx = blockIdx.x * 512 + threadIdx.x;     // < 49152
        int j  = idx & 1;
        int l  = (idx >> 1) & 31;
        int ni = (idx >> 6) & 15;
        int s  = (idx >> 10) & 15;
        int k  = idx >> 14;
        int c  = 8*s + (l & 3) + 4*j;
        int d  = (l >> 2) + 8*ni;
        g_WB[idx] = tf32f(w[k*16384 + c*128 + d]);
    } else {
        int t = threadIdx.x;
        if (t < Nn) {
            float s = 0.f;
            #pragma unroll
            for (int m = 0; m < Nn; ++m) s += adj[t*Nn + m];
            dinv[t] = rsqrtf(s);
        }
        __syncthreads();
        if (t < Nn*Nn) {
            int n = t / Nn, m = t % Nn;
            Ls[t] = (n == m ? 1.f : 0.f) - dinv[n] * adj[t] * dinv[m];
        }
        __syncthreads();
        if (t < Nn*Nn) {
            int n = t / Nn, m = t % Nn;
            float a = 0.f;
            #pragma unroll
            for (int jx = 0; jx < Nn; ++jx) a = fmaf(Ls[n*Nn + jx], Ls[jx*Nn + m], a);
            float t2 = 2.f * a - (n == m ? 1.f : 0.f);
            g_L12[t] = make_float4(Ls[t], Ls[t], t2, t2);
        }
    }
}

// ---------------------------------------------------------------------------
// GEMM chunk: 16 k-steps, A frags from smem (2x LDS.64 per mi), B frags from
// gmem (coalesced LDG.64, L1-resident after wave 1), depth-1 double buffer.
// ---------------------------------------------------------------------------
template<int STR>
__device__ __forceinline__ void gemm_chunk(const float* Ab, const float* Bb,
                                           float acc[2][8][4]) {
    uint2 A[2][2][2];
    uint2 B[2][8];
    #pragma unroll
    for (int mi = 0; mi < 2; ++mi) {
        A[0][mi][0] = *(const uint2*)(Ab + mi*16*STR);
        A[0][mi][1] = *(const uint2*)(Ab + mi*16*STR + 8*STR);
    }
    #pragma unroll
    for (int ni = 0; ni < 8; ++ni) B[0][ni] = *(const uint2*)(Bb + ni*64);
    #pragma unroll
    for (int s = 0; s < 16; ++s) {
        const int cur = s & 1, nxt = cur ^ 1;
        if (s < 15) {
            const float* An = Ab + (s + 1) * 8;
            #pragma unroll
            for (int mi = 0; mi < 2; ++mi) {
                A[nxt][mi][0] = *(const uint2*)(An + mi*16*STR);
                A[nxt][mi][1] = *(const uint2*)(An + mi*16*STR + 8*STR);
            }
            const float* Bx = Bb + (s + 1) * 1024;
            #pragma unroll
            for (int ni = 0; ni < 8; ++ni) B[nxt][ni] = *(const uint2*)(Bx + ni*64);
        }
        #pragma unroll
        for (int mi = 0; mi < 2; ++mi)
            #pragma unroll
            for (int ni = 0; ni < 8; ++ni)
                mma_tf32(acc[mi][ni],
                         A[cur][mi][0].x, A[cur][mi][1].x,
                         A[cur][mi][0].y, A[cur][mi][1].y,
                         B[cur][ni].x, B[cur][ni].y);
    }
}

// ---------------------------------------------------------------------------
// Main kernel
// ---------------------------------------------------------------------------
__global__ void __launch_bounds__(THREADS, 1)
graphcheb(const float* __restrict__ x, const float* __restrict__ bias,
          float* __restrict__ out) {
    extern __shared__ float sm[];
    float* sXU = sm + SF_XU;
    float* sU  = sm + SF_U;
    const ulonglong2* sL = (const ulonglong2*)(sm + SF_L);
    float* sB  = sm + SF_BIAS;

    const int t    = threadIdx.x;
    const int lane = t & 31;
    const int warp = t >> 5;
    const int g    = lane >> 2;
    const int tq   = lane & 3;

    const int rg0    = blockIdx.x * 128;
    const int bstart = rg0 / Nn;
    const int phase  = rg0 - bstart * Nn;
    const int nb     = (rg0 + 127) / Nn - bstart + 1;   // 8 or 9 batches staged

    // ---- prologue: x rows -> sXU (tf32, column-pair-permuted), L, bias ----
    {
        const float* xg = x + (size_t)bstart * 2176;
        const int nblk = nb * 17 * 16;
        for (int i = t; i < nblk; i += THREADS) {
            int row = i >> 4, blk = i & 15;
            const float* p = xg + row*128 + blk*8;
            float4 v0 = *(const float4*)p;
            float4 v1 = *(const float4*)(p + 4);
            uint64_t* o = (uint64_t*)(sXU + row*XSTR + blk*8);
            o[0] = pack2f(tf32f(v0.x), tf32f(v1.x));
            o[1] = pack2f(tf32f(v0.y), tf32f(v1.y));
            o[2] = pack2f(tf32f(v0.z), tf32f(v1.z));
            o[3] = pack2f(tf32f(v0.w), tf32f(v1.w));
        }
        for (int i = t; i < Nn*Nn; i += THREADS)
            ((float4*)(sm + SF_L))[i] = g_L12[i];
        if (t < Dd) sB[t] = bias[t];
    }
    __syncthreads();

    // ---- aggregation (one pass, both U1 and U2): item = (batch, col-pair) ----
    {
        const int items = nb * 64;
        for (int it = t; it < items; it += THREADS) {
            const int bb = it >> 6, p = it & 63;
            const float* xb = sXU + bb*17*XSTR + 2*p;
            uint64_t x2[Nn];
            #pragma unroll
            for (int m = 0; m < Nn; ++m) x2[m] = *(const uint64_t*)(xb + m*XSTR);
            const int rb = bb*17 - phase;
            #pragma unroll 1
            for (int n = 0; n < Nn; ++n) {
                const int r = rb + n;
                if ((unsigned)r >= 128u) continue;
                uint64_t a1 = 0ull, a2 = 0ull;
                const ulonglong2* Ln = sL + n*Nn;
                #pragma unroll
                for (int m = 0; m < Nn; ++m) {
                    ulonglong2 l = Ln[m];          // LDS.128 broadcast {l1,l1 | t2,t2}
                    fma2(a1, x2[m], l.x);
                    fma2(a2, x2[m], l.y);
                }
                float f0, f1;
                unpack2(a1, f0, f1);
                *(uint64_t*)(sU + r*USTR + 2*p) =
                    pack2i(cvt_tf32(f0), cvt_tf32(f1));
                unpack2(a2, f0, f1);
                *(uint64_t*)(sU + r*USTR + 128 + 2*p) =
                    pack2i(cvt_tf32(f0), cvt_tf32(f1));
            }
        }
    }
    __syncthreads();

    // ---- GEMM: 3 chunks back-to-back, no further barriers ----
    if (warp < 8) {
        const int mw = warp >> 1, nw = warp & 1;
        const int r0 = 32 * mw;
        const int arow = r0 + g;
        float acc[2][8][4];
        #pragma unroll
        for (int mi = 0; mi < 2; ++mi)
            #pragma unroll
            for (int ni = 0; ni < 8; ++ni)
                #pragma unroll
                for (int j = 0; j < 4; ++j) acc[mi][ni][j] = 0.f;

        gemm_chunk<XSTR>(sXU + (phase + arow)*XSTR + 2*tq,
                         g_WB + (0*256 + 8*nw)*64 + lane*2, acc);
        gemm_chunk<USTR>(sU + arow*USTR + 2*tq,
                         g_WB + (1*256 + 8*nw)*64 + lane*2, acc);
        gemm_chunk<USTR>(sU + arow*USTR + 128 + 2*tq,
                         g_WB + (2*256 + 8*nw)*64 + lane*2, acc);

        // ---- epilogue: bias + relu ----
        const int d0c = 64 * nw;
        #pragma unroll
        for (int ni = 0; ni < 8; ++ni) {
            const int col = d0c + 8*ni + 2*tq;
            const float2 bv = *(const float2*)(sB + col);
            #pragma unroll
            for (int mi = 0; mi < 2; ++mi) {
                const int rr = rg0 + r0 + 16*mi + g;
                float2 v0, v1;
                v0.x = fmaxf(acc[mi][ni][0] + bv.x, 0.f);
                v0.y = fmaxf(acc[mi][ni][1] + bv.y, 0.f);
                v1.x = fmaxf(acc[mi][ni][2] + bv.x, 0.f);
                v1.y = fmaxf(acc[mi][ni][3] + bv.y, 0.f);
                *(float2*)(out + (size_t)rr*Dd + col)       = v0;
                *(float2*)(out + (size_t)(rr + 8)*Dd + col) = v1;
            }
        }
    }
}

// ---------------------------------------------------------------------------
extern "C" void kernel_launch(void* const* d_in, const int* in_sizes, int n_in,
                              void* d_out, int out_size) {
    const float* x    = (const float*)d_in[0];   // [16384,17,128]
    const float* adj  = (const float*)d_in[1];   // [17,17]
    const float* w    = (const float*)d_in[2];   // [3,1,128,128]
    const float* bias = (const float*)d_in[3];   // [1,1,128]
    float* out = (float*)d_out;                  // [16384,17,128]

    cudaFuncSetAttribute(graphcheb,
                         cudaFuncAttributeMaxDynamicSharedMemorySize, SMEM_BYTES);

    setup_kernel<<<97, 512>>>(adj, w);
    graphcheb<<<(Bn*Nn)/128, THREADS, SMEM_BYTES>>>(x, bias, out);
}